// round 1
// baseline (speedup 1.0000x reference)
#include <cuda_runtime.h>

#define B_TOTAL 16384
#define F_FIELDS 39
#define E_DIM 64
#define U_DIM 128
#define BTILE 128

// feat_sum scratch (B x E fp32) — device global, no allocation.
__device__ float g_fsum[B_TOTAL * E_DIM];

__device__ __forceinline__ unsigned f2tf(float x) {
    unsigned y;
    asm("cvt.rna.tf32.f32 %0, %1;" : "=r"(y) : "f"(x));
    return y;
}

// ---------------- Kernel 1: feat_sum over F ----------------
__global__ void fsum_kernel(const float* __restrict__ embeds) {
    int idx = blockIdx.x * blockDim.x + threadIdx.x;   // 262144 threads
    int b = idx >> 4;
    int e4 = idx & 15;
    const float4* p = reinterpret_cast<const float4*>(embeds)
                      + (size_t)b * (F_FIELDS * E_DIM / 4) + e4;
    float4 s = make_float4(0.f, 0.f, 0.f, 0.f);
#pragma unroll
    for (int f = 0; f < F_FIELDS; ++f) {
        float4 v = p[f * (E_DIM / 4)];
        s.x += v.x; s.y += v.y; s.z += v.z; s.w += v.w;
    }
    reinterpret_cast<float4*>(g_fsum)[idx] = s;
}

// ---------------- Kernel 2: lp[b,u] = f^T W_u f via tf32 mma ----------------
// Block: 256 threads (8 warps), handles BTILE=128 rows x all 128 u.
// Warp w owns rows w*16 .. w*16+15. A-fragments of F kept in registers for
// all u. W_u staged in smem (tf32, XOR-swizzled -> conflict-free B loads).
__global__ void __launch_bounds__(256, 1)
quad_kernel(const float* __restrict__ W, float* __restrict__ out) {
    __shared__ unsigned sF[BTILE * 64];   // 32 KB, tf32 bits of F tile
    __shared__ unsigned sW[64 * 64];      // 16 KB, tf32 bits of W_u (swizzled)

    const int tid  = threadIdx.x;
    const int warp = tid >> 5;
    const int lane = tid & 31;
    const int l4 = lane >> 2;    // groupID
    const int k4 = lane & 3;     // threadID_in_group
    const int b0 = blockIdx.x * BTILE;

    // ---- load F tile (128x64 fp32 -> tf32) ----
#pragma unroll
    for (int t = 0; t < 8; ++t) {
        int lin = tid + t * 256;              // float4 index, 0..2047
        int row = lin >> 4;
        int c4  = (lin & 15) << 2;
        float4 v = *reinterpret_cast<const float4*>(
            g_fsum + (size_t)(b0 + row) * E_DIM + c4);
        uint4 q = make_uint4(f2tf(v.x), f2tf(v.y), f2tf(v.z), f2tf(v.w));
        *reinterpret_cast<uint4*>(sF + row * 64 + c4) = q;
    }
    __syncthreads();

    // ---- A fragments (m16k8 x 8 k-steps), resident across all u ----
    const int r0 = warp * 16 + l4;
    unsigned a[8][4];
#pragma unroll
    for (int kk = 0; kk < 8; ++kk) {
        a[kk][0] = sF[r0 * 64 + kk * 8 + k4];
        a[kk][1] = sF[(r0 + 8) * 64 + kk * 8 + k4];
        a[kk][2] = sF[r0 * 64 + kk * 8 + k4 + 4];
        a[kk][3] = sF[(r0 + 8) * 64 + kk * 8 + k4 + 4];
    }
    // ---- epilogue f values matching C-fragment columns ----
    float fe0[16], fe1[16];
#pragma unroll
    for (int n = 0; n < 8; ++n) {
        int j = n * 8 + k4 * 2;
        fe0[2 * n]     = __uint_as_float(sF[r0 * 64 + j]);
        fe0[2 * n + 1] = __uint_as_float(sF[r0 * 64 + j + 1]);
        fe1[2 * n]     = __uint_as_float(sF[(r0 + 8) * 64 + j]);
        fe1[2 * n + 1] = __uint_as_float(sF[(r0 + 8) * 64 + j + 1]);
    }

    // ---- prefetch W_0 into registers ----
    float4 pf[4];
#pragma unroll
    for (int t = 0; t < 4; ++t)
        pf[t] = reinterpret_cast<const float4*>(W)[tid + t * 256];

    for (int u = 0; u < U_DIM; ++u) {
        __syncthreads();   // previous iteration done reading sW
        // stage W_u: tf32-round + XOR swizzle (j ^= (i&3)*8) -> conflict-free
#pragma unroll
        for (int t = 0; t < 4; ++t) {
            int lin = tid + t * 256;           // float4 index in 64x64
            int i = lin >> 4;
            int j = (lin & 15) << 2;
            int jsw = j ^ ((i & 3) << 3);
            uint4 q = make_uint4(f2tf(pf[t].x), f2tf(pf[t].y),
                                 f2tf(pf[t].z), f2tf(pf[t].w));
            *reinterpret_cast<uint4*>(sW + i * 64 + jsw) = q;
        }
        __syncthreads();

        // prefetch W_{u+1} (overlaps with compute below)
        if (u + 1 < U_DIM) {
            const float4* wn = reinterpret_cast<const float4*>(
                W + (size_t)(u + 1) * E_DIM * E_DIM);
#pragma unroll
            for (int t = 0; t < 4; ++t) pf[t] = wn[tid + t * 256];
        }

        float acc0 = 0.f, acc1 = 0.f;
#pragma unroll
        for (int n = 0; n < 8; ++n) {
            float c0 = 0.f, c1 = 0.f, c2 = 0.f, c3 = 0.f;
#pragma unroll
            for (int kk = 0; kk < 8; ++kk) {
                int jb = (n * 8 + l4) ^ (k4 << 3);   // swizzled column
                unsigned bf0 = sW[(kk * 8 + k4) * 64 + jb];
                unsigned bf1 = sW[(kk * 8 + k4 + 4) * 64 + jb];
                asm volatile(
                    "mma.sync.aligned.m16n8k8.row.col.f32.tf32.tf32.f32 "
                    "{%0,%1,%2,%3}, {%4,%5,%6,%7}, {%8,%9}, {%0,%1,%2,%3};"
                    : "+f"(c0), "+f"(c1), "+f"(c2), "+f"(c3)
                    : "r"(a[kk][0]), "r"(a[kk][1]), "r"(a[kk][2]), "r"(a[kk][3]),
                      "r"(bf0), "r"(bf1));
            }
            acc0 = fmaf(c0, fe0[2 * n], fmaf(c1, fe0[2 * n + 1], acc0));
            acc1 = fmaf(c2, fe1[2 * n], fmaf(c3, fe1[2 * n + 1], acc1));
        }
        // reduce over the 4 lanes sharing the same row (lane%4 groups)
        acc0 += __shfl_xor_sync(0xffffffffu, acc0, 1);
        acc0 += __shfl_xor_sync(0xffffffffu, acc0, 2);
        acc1 += __shfl_xor_sync(0xffffffffu, acc1, 1);
        acc1 += __shfl_xor_sync(0xffffffffu, acc1, 2);
        if (k4 == 0) {
            out[(size_t)(b0 + r0) * U_DIM + u]     = acc0;
            out[(size_t)(b0 + r0 + 8) * U_DIM + u] = acc1;
        }
    }
}

extern "C" void kernel_launch(void* const* d_in, const int* in_sizes, int n_in,
                              void* d_out, int out_size) {
    const float* embeds = (const float*)d_in[0];   // (16384, 39, 64)
    const float* W      = (const float*)d_in[1];   // (128, 64, 64)
    float* out          = (float*)d_out;           // (16384, 128)

    fsum_kernel<<<(B_TOTAL * (E_DIM / 4)) / 256, 256>>>(embeds);
    quad_kernel<<<B_TOTAL / BTILE, 256>>>(W, out);
}

// round 2
// speedup vs baseline: 1.0004x; 1.0004x over previous
#include <cuda_runtime.h>

#define B_TOTAL 16384
#define F_FIELDS 39
#define E_DIM 64
#define U_DIM 128
#define BTILE 128

// feat_sum scratch (B x E fp32) — device global, no allocation.
__device__ float g_fsum[B_TOTAL * E_DIM];

__device__ __forceinline__ unsigned f2tf(float x) {
    unsigned y;
    asm("cvt.rna.tf32.f32 %0, %1;" : "=r"(y) : "f"(x));
    return y;
}

// ---------------- Kernel 1: feat_sum over F ----------------
__global__ void fsum_kernel(const float* __restrict__ embeds) {
    int idx = blockIdx.x * blockDim.x + threadIdx.x;   // 262144 threads
    int b = idx >> 4;
    int e4 = idx & 15;
    const float4* p = reinterpret_cast<const float4*>(embeds)
                      + (size_t)b * (F_FIELDS * E_DIM / 4) + e4;
    float4 s = make_float4(0.f, 0.f, 0.f, 0.f);
#pragma unroll
    for (int f = 0; f < F_FIELDS; ++f) {
        float4 v = p[f * (E_DIM / 4)];
        s.x += v.x; s.y += v.y; s.z += v.z; s.w += v.w;
    }
    reinterpret_cast<float4*>(g_fsum)[idx] = s;
}

// ---------------- Kernel 2: lp[b,u] = f^T W_u f via tf32 mma ----------------
// Block: 256 threads (8 warps), handles BTILE=128 rows x all 128 u.
// Warp w owns rows w*16 .. w*16+15. A-fragments of F kept in registers for
// all u. W_u staged in smem (tf32, XOR-swizzled -> conflict-free B loads).
__global__ void __launch_bounds__(256, 1)
quad_kernel(const float* __restrict__ W, float* __restrict__ out) {
    __shared__ unsigned sF[BTILE * 64];   // 32 KB, tf32 bits of F tile
    __shared__ unsigned sW[64 * 64];      // 16 KB, tf32 bits of W_u (swizzled)

    const int tid  = threadIdx.x;
    const int warp = tid >> 5;
    const int lane = tid & 31;
    const int l4 = lane >> 2;    // groupID
    const int k4 = lane & 3;     // threadID_in_group
    const int b0 = blockIdx.x * BTILE;

    // ---- load F tile (128x64 fp32 -> tf32) ----
#pragma unroll
    for (int t = 0; t < 8; ++t) {
        int lin = tid + t * 256;              // float4 index, 0..2047
        int row = lin >> 4;
        int c4  = (lin & 15) << 2;
        float4 v = *reinterpret_cast<const float4*>(
            g_fsum + (size_t)(b0 + row) * E_DIM + c4);
        uint4 q = make_uint4(f2tf(v.x), f2tf(v.y), f2tf(v.z), f2tf(v.w));
        *reinterpret_cast<uint4*>(sF + row * 64 + c4) = q;
    }
    __syncthreads();

    // ---- A fragments (m16k8 x 8 k-steps), resident across all u ----
    const int r0 = warp * 16 + l4;
    unsigned a[8][4];
#pragma unroll
    for (int kk = 0; kk < 8; ++kk) {
        a[kk][0] = sF[r0 * 64 + kk * 8 + k4];
        a[kk][1] = sF[(r0 + 8) * 64 + kk * 8 + k4];
        a[kk][2] = sF[r0 * 64 + kk * 8 + k4 + 4];
        a[kk][3] = sF[(r0 + 8) * 64 + kk * 8 + k4 + 4];
    }
    // ---- epilogue f values matching C-fragment columns ----
    float fe0[16], fe1[16];
#pragma unroll
    for (int n = 0; n < 8; ++n) {
        int j = n * 8 + k4 * 2;
        fe0[2 * n]     = __uint_as_float(sF[r0 * 64 + j]);
        fe0[2 * n + 1] = __uint_as_float(sF[r0 * 64 + j + 1]);
        fe1[2 * n]     = __uint_as_float(sF[(r0 + 8) * 64 + j]);
        fe1[2 * n + 1] = __uint_as_float(sF[(r0 + 8) * 64 + j + 1]);
    }

    // ---- prefetch W_0 into registers ----
    float4 pf[4];
#pragma unroll
    for (int t = 0; t < 4; ++t)
        pf[t] = reinterpret_cast<const float4*>(W)[tid + t * 256];

    for (int u = 0; u < U_DIM; ++u) {
        __syncthreads();   // previous iteration done reading sW
        // stage W_u: tf32-round + XOR swizzle (j ^= (i&3)*8) -> conflict-free
#pragma unroll
        for (int t = 0; t < 4; ++t) {
            int lin = tid + t * 256;           // float4 index in 64x64
            int i = lin >> 4;
            int j = (lin & 15) << 2;
            int jsw = j ^ ((i & 3) << 3);
            uint4 q = make_uint4(f2tf(pf[t].x), f2tf(pf[t].y),
                                 f2tf(pf[t].z), f2tf(pf[t].w));
            *reinterpret_cast<uint4*>(sW + i * 64 + jsw) = q;
        }
        __syncthreads();

        // prefetch W_{u+1} (overlaps with compute below)
        if (u + 1 < U_DIM) {
            const float4* wn = reinterpret_cast<const float4*>(
                W + (size_t)(u + 1) * E_DIM * E_DIM);
#pragma unroll
            for (int t = 0; t < 4; ++t) pf[t] = wn[tid + t * 256];
        }

        float acc0 = 0.f, acc1 = 0.f;
#pragma unroll
        for (int n = 0; n < 8; ++n) {
            float c0 = 0.f, c1 = 0.f, c2 = 0.f, c3 = 0.f;
#pragma unroll
            for (int kk = 0; kk < 8; ++kk) {
                int jb = (n * 8 + l4) ^ (k4 << 3);   // swizzled column
                unsigned bf0 = sW[(kk * 8 + k4) * 64 + jb];
                unsigned bf1 = sW[(kk * 8 + k4 + 4) * 64 + jb];
                asm volatile(
                    "mma.sync.aligned.m16n8k8.row.col.f32.tf32.tf32.f32 "
                    "{%0,%1,%2,%3}, {%4,%5,%6,%7}, {%8,%9}, {%0,%1,%2,%3};"
                    : "+f"(c0), "+f"(c1), "+f"(c2), "+f"(c3)
                    : "r"(a[kk][0]), "r"(a[kk][1]), "r"(a[kk][2]), "r"(a[kk][3]),
                      "r"(bf0), "r"(bf1));
            }
            acc0 = fmaf(c0, fe0[2 * n], fmaf(c1, fe0[2 * n + 1], acc0));
            acc1 = fmaf(c2, fe1[2 * n], fmaf(c3, fe1[2 * n + 1], acc1));
        }
        // reduce over the 4 lanes sharing the same row (lane%4 groups)
        acc0 += __shfl_xor_sync(0xffffffffu, acc0, 1);
        acc0 += __shfl_xor_sync(0xffffffffu, acc0, 2);
        acc1 += __shfl_xor_sync(0xffffffffu, acc1, 1);
        acc1 += __shfl_xor_sync(0xffffffffu, acc1, 2);
        if (k4 == 0) {
            out[(size_t)(b0 + r0) * U_DIM + u]     = acc0;
            out[(size_t)(b0 + r0 + 8) * U_DIM + u] = acc1;
        }
    }
}

extern "C" void kernel_launch(void* const* d_in, const int* in_sizes, int n_in,
                              void* d_out, int out_size) {
    const float* embeds = (const float*)d_in[0];   // (16384, 39, 64)
    const float* W      = (const float*)d_in[1];   // (128, 64, 64)
    float* out          = (float*)d_out;           // (16384, 128)

    fsum_kernel<<<(B_TOTAL * (E_DIM / 4)) / 256, 256>>>(embeds);
    quad_kernel<<<B_TOTAL / BTILE, 256>>>(W, out);
}

// round 4
// speedup vs baseline: 1.1139x; 1.1135x over previous
#include <cuda_runtime.h>
#include <cstdint>
#include <math.h>

#define B_TOTAL 16384
#define F_FIELDS 39
#define E_DIM 64
#define U_DIM 128
#define BTILE 128
#define NPAIR 2080
#define KPAD  2112
#define NCHUNK 33
#define FSTR 65
#define ASTR 68
#define BSTR 68
#define ABUF 8704            // 128*68 floats per A/B buffer
#define SMEM_FLOATS (8320 + 2*ABUF + 2*ABUF + KPAD)
#define SMEM_BYTES  (SMEM_FLOATS * 4)

__device__ float    g_fsum[B_TOTAL * E_DIM];
__device__ unsigned g_T[U_DIM * KPAD];     // rna-tf32 bits of packed symmetric W
__device__ unsigned g_pair[KPAD];          // (i<<8)|j per packed k index

__device__ __forceinline__ unsigned f2tf(float x) {
    unsigned y; asm("cvt.rna.tf32.f32 %0, %1;" : "=r"(y) : "f"(x)); return y;
}
__device__ __forceinline__ uint32_t smem_u32(const void* p) {
    uint32_t a;
    asm("{ .reg .u64 t; cvta.to.shared.u64 t, %1; cvt.u32.u64 %0, t; }" : "=r"(a) : "l"(p));
    return a;
}
__device__ __forceinline__ void cp16(uint32_t dst, const void* src) {
    asm volatile("cp.async.cg.shared.global [%0], [%1], 16;" :: "r"(dst), "l"(src) : "memory");
}
__device__ __forceinline__ void cp_commit() {
    asm volatile("cp.async.commit_group;" ::: "memory");
}
__device__ __forceinline__ void cp_wait0() {
    asm volatile("cp.async.wait_group 0;" ::: "memory");
}
__device__ __forceinline__ void mma8(float* c, const unsigned* a, unsigned b0, unsigned b1) {
    asm volatile(
        "mma.sync.aligned.m16n8k8.row.col.f32.tf32.tf32.f32 "
        "{%0,%1,%2,%3}, {%4,%5,%6,%7}, {%8,%9}, {%0,%1,%2,%3};"
        : "+f"(c[0]), "+f"(c[1]), "+f"(c[2]), "+f"(c[3])
        : "r"(a[0]), "r"(a[1]), "r"(a[2]), "r"(a[3]), "r"(b0), "r"(b1));
}

// ---------------- pair table: packed upper-triangular (i<=j) ----------------
__global__ void pairs_kernel() {
    int t = blockIdx.x * blockDim.x + threadIdx.x;
    if (t >= KPAD) return;
    unsigned val = 0;
    if (t < NPAIR) {
        double d = 129.0 * 129.0 - 8.0 * (double)t;
        int i = (int)((129.0 - sqrt(d)) * 0.5);
        if (i < 0) i = 0; if (i > 63) i = 63;
        while (i > 0  && i * (129 - i) / 2 > t) --i;
        while (i < 63 && (i + 1) * (128 - i) / 2 <= t) ++i;
        int j = i + (t - i * (129 - i) / 2);
        val = ((unsigned)i << 8) | (unsigned)j;
    }
    g_pair[t] = val;
}

// ---------------- feat_sum over F ----------------
__global__ void fsum_kernel(const float* __restrict__ embeds) {
    int idx = blockIdx.x * blockDim.x + threadIdx.x;
    int b = idx >> 4;
    int e4 = idx & 15;
    const float4* p = reinterpret_cast<const float4*>(embeds)
                      + (size_t)b * (F_FIELDS * E_DIM / 4) + e4;
    float4 s = make_float4(0.f, 0.f, 0.f, 0.f);
#pragma unroll
    for (int f = 0; f < F_FIELDS; ++f) {
        float4 v = p[f * (E_DIM / 4)];
        s.x += v.x; s.y += v.y; s.z += v.z; s.w += v.w;
    }
    reinterpret_cast<float4*>(g_fsum)[idx] = s;
}

// ---------------- packed symmetric T[u,k] = rna_tf32(W_ij + W_ji) ----------------
__global__ void tconv_kernel(const float* __restrict__ W) {
    int idx = blockIdx.x * blockDim.x + threadIdx.x;   // u*KPAD + k
    int u = idx / KPAD;
    int k = idx - u * KPAD;
    float v = 0.f;
    if (k < NPAIR) {
        unsigned p = g_pair[k];
        int i = p >> 8, j = p & 255;
        v = W[u * 4096 + i * 64 + j];
        if (i != j) v += W[u * 4096 + j * 64 + i];
    }
    g_T[idx] = f2tf(v);
}

// ---------------- main GEMM: C[128b x 128u] += A[128 x 64] * B[64 x 128] ----------------
__global__ void __launch_bounds__(256, 1)
quad_kernel(float* __restrict__ out) {
    extern __shared__ float sm[];
    float*    sF = sm;                         // 128*65
    float*    sA = sm + 8320;                  // 2 * 8704
    float*    sB = sm + 8320 + 2 * ABUF;       // 2 * 8704
    unsigned* sP = (unsigned*)(sm + 8320 + 4 * ABUF);  // 2112

    const int tid  = threadIdx.x;
    const int lane = tid & 31;
    const int warp = tid >> 5;
    const int l4 = lane >> 2, k4 = lane & 3;
    const int wm = warp & 3;          // 4-way m split
    const int wn = warp >> 2;         // 2-way n split
    const int row_base = wm * 32;
    const int col_base = wn * 64;
    const int b0 = blockIdx.x * BTILE;
    const int r  = tid & 127;
    const int kh = (tid >> 7) * 32;

    const uint32_t sB_u = smem_u32(sB);

    // ---- stage f tile (padded stride 65 -> conflict-free column reads) ----
    {
        const float4* src = reinterpret_cast<const float4*>(
            g_fsum + (size_t)(b0 + r) * E_DIM + kh);
        float tmp[32];
#pragma unroll
        for (int t = 0; t < 8; ++t) {
            float4 v = src[t];
            tmp[4*t] = v.x; tmp[4*t+1] = v.y; tmp[4*t+2] = v.z; tmp[4*t+3] = v.w;
        }
#pragma unroll
        for (int t = 0; t < 32; ++t) sF[r * FSTR + kh + t] = tmp[t];
    }
    for (int k = tid; k < KPAD; k += 256) sP[k] = g_pair[k];

    // ---- prologue: B chunk 0 ----
    {
        const unsigned* src = g_T + (size_t)r * KPAD + kh;
        uint32_t dst = sB_u + (uint32_t)(r * BSTR + kh) * 4u;
#pragma unroll
        for (int q = 0; q < 8; ++q) cp16(dst + 16u * q, src + 4 * q);
        cp_commit();
    }
    cp_wait0();
    __syncthreads();

    // ---- gen A chunk 0 ----
    {
        const int fb = r * FSTR;
        float* dst = sA + r * ASTR + kh;
#pragma unroll
        for (int q = 0; q < 8; ++q) {
            unsigned p0 = sP[kh + 4*q + 0], p1 = sP[kh + 4*q + 1];
            unsigned p2 = sP[kh + 4*q + 2], p3 = sP[kh + 4*q + 3];
            float4 v;
            v.x = __uint_as_float(f2tf(sF[fb + (p0 >> 8)] * sF[fb + (p0 & 255)]));
            v.y = __uint_as_float(f2tf(sF[fb + (p1 >> 8)] * sF[fb + (p1 & 255)]));
            v.z = __uint_as_float(f2tf(sF[fb + (p2 >> 8)] * sF[fb + (p2 & 255)]));
            v.w = __uint_as_float(f2tf(sF[fb + (p3 >> 8)] * sF[fb + (p3 & 255)]));
            *reinterpret_cast<float4*>(dst + 4*q) = v;
        }
    }
    __syncthreads();

    float acc[2][8][4];
#pragma unroll
    for (int mt = 0; mt < 2; ++mt)
#pragma unroll
        for (int nt = 0; nt < 8; ++nt)
#pragma unroll
            for (int x = 0; x < 4; ++x) acc[mt][nt][x] = 0.f;

#pragma unroll 1
    for (int c = 0; c < NCHUNK; ++c) {
        const int cur = c & 1, nxt = cur ^ 1;

        // stage B(c+1) into the other buffer (free since mma(c-1) finished)
        if (c + 1 < NCHUNK) {
            const unsigned* src = g_T + (size_t)r * KPAD + (c + 1) * 64 + kh;
            uint32_t dst = sB_u + (uint32_t)(nxt * ABUF + r * BSTR + kh) * 4u;
#pragma unroll
            for (int q = 0; q < 8; ++q) cp16(dst + 16u * q, src + 4 * q);
            cp_commit();
        }

        // ---- mma over chunk c ----
        const float* A = sA + cur * ABUF;
        const float* B = sB + cur * ABUF;
#pragma unroll
        for (int kk = 0; kk < 8; ++kk) {
            unsigned a[2][4];
#pragma unroll
            for (int mt = 0; mt < 2; ++mt) {
                const int rr = (row_base + mt * 16 + l4) * ASTR + kk * 8 + k4;
                a[mt][0] = __float_as_uint(A[rr]);
                a[mt][1] = __float_as_uint(A[rr + 8 * ASTR]);
                a[mt][2] = __float_as_uint(A[rr + 4]);
                a[mt][3] = __float_as_uint(A[rr + 8 * ASTR + 4]);
            }
#pragma unroll
            for (int nt = 0; nt < 8; ++nt) {
                const int bb = (col_base + nt * 8 + l4) * BSTR + kk * 8 + k4;
                unsigned bf0 = __float_as_uint(B[bb]);
                unsigned bf1 = __float_as_uint(B[bb + 4]);
                mma8(acc[0][nt], a[0], bf0, bf1);
                mma8(acc[1][nt], a[1], bf0, bf1);
            }
        }

        // ---- gen A(c+1) into the other buffer (overlaps tensor pipe) ----
        if (c + 1 < NCHUNK) {
            const int kb = (c + 1) * 64 + kh;
            const int fb = r * FSTR;
            float* dst = sA + nxt * ABUF + r * ASTR + kh;
#pragma unroll
            for (int q = 0; q < 8; ++q) {
                unsigned p0 = sP[kb + 4*q + 0], p1 = sP[kb + 4*q + 1];
                unsigned p2 = sP[kb + 4*q + 2], p3 = sP[kb + 4*q + 3];
                float4 v;
                v.x = __uint_as_float(f2tf(sF[fb + (p0 >> 8)] * sF[fb + (p0 & 255)]));
                v.y = __uint_as_float(f2tf(sF[fb + (p1 >> 8)] * sF[fb + (p1 & 255)]));
                v.z = __uint_as_float(f2tf(sF[fb + (p2 >> 8)] * sF[fb + (p2 & 255)]));
                v.w = __uint_as_float(f2tf(sF[fb + (p3 >> 8)] * sF[fb + (p3 & 255)]));
                *reinterpret_cast<float4*>(dst + 4*q) = v;
            }
        }
        cp_wait0();
        __syncthreads();
    }

    // ---- epilogue: direct STG of C fragments ----
#pragma unroll
    for (int mt = 0; mt < 2; ++mt) {
#pragma unroll
        for (int nt = 0; nt < 8; ++nt) {
            const int rr = b0 + row_base + mt * 16 + l4;
            const int cc = col_base + nt * 8 + k4 * 2;
            float2 v0 = make_float2(acc[mt][nt][0], acc[mt][nt][1]);
            float2 v1 = make_float2(acc[mt][nt][2], acc[mt][nt][3]);
            *reinterpret_cast<float2*>(out + (size_t)rr * U_DIM + cc) = v0;
            *reinterpret_cast<float2*>(out + (size_t)(rr + 8) * U_DIM + cc) = v1;
        }
    }
}

extern "C" void kernel_launch(void* const* d_in, const int* in_sizes, int n_in,
                              void* d_out, int out_size) {
    const float* embeds = (const float*)d_in[0];   // (16384, 39, 64)
    const float* W      = (const float*)d_in[1];   // (128, 64, 64)
    float* out          = (float*)d_out;           // (16384, 128)

    static int smem_set = 0;
    if (!smem_set) {
        cudaFuncSetAttribute(quad_kernel,
                             cudaFuncAttributeMaxDynamicSharedMemorySize, SMEM_BYTES);
        smem_set = 1;
    }

    pairs_kernel<<<(KPAD + 255) / 256, 256>>>();
    fsum_kernel<<<(B_TOTAL * (E_DIM / 4)) / 256, 256>>>(embeds);
    tconv_kernel<<<(U_DIM * KPAD) / 256, 256>>>(W);
    quad_kernel<<<B_TOTAL / BTILE, 256, SMEM_BYTES>>>(out);
}